// round 8
// baseline (speedup 1.0000x reference)
#include <cuda_runtime.h>

#define Bv 128
#define Tv 1024
#define Nv 64
#define U 8

// Scratch (no cudaMalloc allowed). g_ctr wraps back to 0 every full run -> graph-safe.
__device__ float g_loss[Bv];
__device__ unsigned g_ctr = 0;

#define FMA_X2(d, a, b, c) \
  asm("fma.rn.f32x2 %0, %1, %2, %3;" : "=l"(d) : "l"(a), "l"(b), "l"(c))
#define ADD_X2(d, a, b) \
  asm("add.rn.f32x2 %0, %1, %2;" : "=l"(d) : "l"(a), "l"(b))

__global__ __launch_bounds__(64) void crf_kernel(
    const float* __restrict__ pot, const int* __restrict__ tags,
    const int* __restrict__ seqlen, const float* __restrict__ K,
    const float* __restrict__ w, float* __restrict__ out) {
  const int b = blockIdx.x;
  const int j = threadIdx.x;           // state 0..63
  const int wid = j >> 5, lane = j & 31;
  const int L = seqlen[b];

  __shared__ float Ksh[Nv * 65];                 // padded for column reads
  __shared__ __align__(16) float fbuf[2][Nv];    // ping-pong scaled forward vector f
  __shared__ float rbuf[2];                      // ping-pong lagged normalizer r
  __shared__ float sbase;                        // C0 broadcast
  __shared__ float redx[2], redm2[2];
  __shared__ int slast;

  const float* potb = pot + (long)b * Tv * Nv;
  const int* tagb = tags + b * Tv;

  for (int i = 0; i < Nv; i++) Ksh[i * 65 + j] = K[i * Nv + j];
  __syncthreads();

  // ---- sequence score: batched loads for MLP (t = j + 64u <= 1023 in-bounds) ----
  int tg[16], tp[16];
#pragma unroll
  for (int u = 0; u < 16; u++) {
    int t = j + 64 * u;
    tg[u] = tagb[t];
    tp[u] = tagb[t > 0 ? t - 1 : 0];
  }
  float pv[16];
#pragma unroll
  for (int u = 0; u < 16; u++) pv[u] = potb[(j + 64 * u) * Nv + tg[u]];
  float sc = 0.f;
#pragma unroll
  for (int u = 0; u < 16; u++) {
    int t = j + 64 * u;
    if (t < L) {
      sc += pv[u];
      if (t >= 1) sc += Ksh[tp[u] * 65 + tg[u]];
    }
  }
#pragma unroll
  for (int o = 16; o > 0; o >>= 1) sc += __shfl_xor_sync(0xffffffffu, sc, o);
  if (lane == 0) redx[wid] = sc;

  // ---- exp(K) column j, packed f32x2 pairs along i ----
  unsigned long long eK2[32];
#pragma unroll
  for (int p = 0; p < 32; p++) {
    float e0 = __expf(Ksh[(2 * p) * 65 + j]);
    float e1 = __expf(Ksh[(2 * p + 1) * 65 + j]);
    asm("mov.b64 %0, {%1, %2};" : "=l"(eK2[p]) : "f"(e0), "f"(e1));
  }

  // ---- init t = 0: f0 = exp(pot0 - C0), C0 = pot[0][0] ----
  float a0 = potb[j];
  if (j == 0) sbase = a0;
  float pc[U], pn[U];
#pragma unroll
  for (int u = 0; u < U; u++) {          // raw pot rows for t = 1..U (clamped)
    int t = 1 + u; if (t > L - 1) t = L - 1;
    pc[u] = potb[t * Nv + j];
  }
  __syncthreads();
  float sscore = redx[0] + redx[1];
  float C0 = sbase;
  float fj = __expf(a0 - C0);            // thread-local last f value (f_{0,0} = 1)
  fbuf[1][j] = fj;
  if (j == 0) rbuf[1] = 1.0f;            // r for step 1 (c_1 = c_0)
  float acc = C0 * 1.4426950408889634f;  // thread0: -log2(c_t), log2 domain
  float lzp = 0.f;                       // thread0: pending log2(f_{t,0})
  __syncthreads();

  // ---- main scan: linear-space scaled forward, no log/exp on the chain.
  //      Normalizer r_t = 1/f_{t,0} (stored value!) -> first-order, stable:
  //      c_{t+1} = c_t / f_{t,0} = exp(-alpha_{t,0}). ----
  for (int tb = 1; tb < L; tb += U) {
    const int nb = tb + U;
#pragma unroll
    for (int u = 0; u < U; u++) {        // prefetch next chunk (clamped, branch-free)
      int t = nb + u; if (t > L - 1) t = L - 1;
      pn[u] = potb[t * Nv + j];
    }
    float ec[U];                          // p_tj = exp(pot) for this chunk (off-chain)
#pragma unroll
    for (int u = 0; u < U; u++) ec[u] = __expf(pc[u]);
#pragma unroll
    for (int u = 0; u < U; u++) {
      const int tt = tb + u;
      if (tt >= L) break;                // uniform across block
      const int rb = tt & 1, wb = rb ^ 1;
      float r_prev = rbuf[rb];           // 1/f_{t-1,0} (written last step)
      float pr = ec[u] * r_prev;         // shadow of the dot

      const ulonglong2* e2 = (const ulonglong2*)fbuf[rb];
      unsigned long long acc4[4] = {0ull, 0ull, 0ull, 0ull};
#pragma unroll
      for (int q = 0; q < 16; q++) {     // 32 packed FMAs = 64 scalar MACs
        ulonglong2 v = e2[q];
        FMA_X2(acc4[(2 * q) & 3], v.x, eK2[2 * q], acc4[(2 * q) & 3]);
        FMA_X2(acc4[(2 * q + 1) & 3], v.y, eK2[2 * q + 1], acc4[(2 * q + 1) & 3]);
      }
      unsigned long long s01, s23, sA;
      ADD_X2(s01, acc4[0], acc4[1]);
      ADD_X2(s23, acc4[2], acc4[3]);
      ADD_X2(sA, s01, s23);
      float slo, shi;
      asm("mov.b64 {%0, %1}, %2;" : "=f"(slo), "=f"(shi) : "l"(sA));
      float s = slo + shi;

      fj = s * pr;                       // f_t,j = exp(alpha_t,j - alpha_{t-1,0})
      fbuf[wb][j] = fj;

      if (j == 0) {                      // off-chain bookkeeping (one step of slack)
        acc += lzp;
        lzp = __log2f(fj);               // log2(f_{t,0})
        float r;
        asm("rcp.approx.f32 %0, %1;" : "=f"(r) : "f"(fj));
        rbuf[wb] = r;                    // 1/f_{t,0}, consumed at step t+1
      }
      __syncthreads();
    }
#pragma unroll
    for (int u = 0; u < U; u++) pc[u] = pn[u];
  }

  // ---- finish: logZ = ln2 * (acc + log2(sum_j f_{L-1,j})) ----
  float se = fj;
#pragma unroll
  for (int o = 16; o > 0; o >>= 1) se += __shfl_xor_sync(0xffffffffu, se, o);
  if (lane == 0) redm2[wid] = se;
  __syncthreads();

  if (j == 0) {
    float sumf = redm2[0] + redm2[1];
    float logZ = 0.6931471805599453f * (acc + __log2f(sumf));
    g_loss[b] = -(sscore - logZ) * w[b];
    __threadfence();
    unsigned old = atomicInc(&g_ctr, Bv - 1);  // wraps to 0 each full run
    slast = (old == (unsigned)(Bv - 1)) ? 1 : 0;
  }
  __syncthreads();
  if (slast) {
    float v = __ldcg(&g_loss[j]) + __ldcg(&g_loss[j + 64]);
#pragma unroll
    for (int o = 16; o > 0; o >>= 1) v += __shfl_xor_sync(0xffffffffu, v, o);
    if (lane == 0) redx[wid] = v;
    __syncthreads();
    if (j == 0) out[0] = (redx[0] + redx[1]) * (1.0f / (float)Bv);
  }
}

extern "C" void kernel_launch(void* const* d_in, const int* in_sizes, int n_in,
                              void* d_out, int out_size) {
  const float* pot    = (const float*)d_in[0];  // [128,1024,64] f32
  const int*   tags   = (const int*)  d_in[1];  // [128,1024] i32
  const int*   seqlen = (const int*)  d_in[2];  // [128] i32
  const float* K      = (const float*)d_in[3];  // [64,64] f32
  const float* w      = (const float*)d_in[4];  // [128] f32
  crf_kernel<<<Bv, Nv>>>(pot, tags, seqlen, K, w, (float*)d_out);
}

// round 9
// speedup vs baseline: 1.2547x; 1.2547x over previous
#include <cuda_runtime.h>

#define Bv 128
#define Tv 1024
#define Nv 64
#define U 8

// Scratch (no cudaMalloc allowed). g_ctr wraps back to 0 every full run -> graph-safe.
__device__ float g_loss[Bv];
__device__ unsigned g_ctr = 0;

#define FMA_X2(d, a, b, c) \
  asm("fma.rn.f32x2 %0, %1, %2, %3;" : "=l"(d) : "l"(a), "l"(b), "l"(c))
#define ADD_X2(d, a, b) \
  asm("add.rn.f32x2 %0, %1, %2;" : "=l"(d) : "l"(a), "l"(b))

__global__ __launch_bounds__(64) void crf_kernel(
    const float* __restrict__ pot, const int* __restrict__ tags,
    const int* __restrict__ seqlen, const float* __restrict__ K,
    const float* __restrict__ w, float* __restrict__ out) {
  const int b = blockIdx.x;
  const int j = threadIdx.x;           // state 0..63
  const int wid = j >> 5, lane = j & 31;
  const int L = seqlen[b];

  __shared__ float Ksh[Nv * 65];                 // padded for column reads
  __shared__ __align__(16) float fbuf[2][Nv];    // ping-pong scaled forward vector f
  __shared__ float sbase;                        // C0 broadcast
  __shared__ float redx[2], redm2[2];
  __shared__ int slast;

  const float* potb = pot + (long)b * Tv * Nv;
  const int* tagb = tags + b * Tv;

  for (int i = 0; i < Nv; i++) Ksh[i * 65 + j] = K[i * Nv + j];
  __syncthreads();

  // ---- sequence score: batched loads for MLP (t = j + 64u <= 1023 in-bounds) ----
  int tg[16], tp[16];
#pragma unroll
  for (int u = 0; u < 16; u++) {
    int t = j + 64 * u;
    tg[u] = tagb[t];
    tp[u] = tagb[t > 0 ? t - 1 : 0];
  }
  float pv[16];
#pragma unroll
  for (int u = 0; u < 16; u++) pv[u] = potb[(j + 64 * u) * Nv + tg[u]];
  float sc = 0.f;
#pragma unroll
  for (int u = 0; u < 16; u++) {
    int t = j + 64 * u;
    if (t < L) {
      sc += pv[u];
      if (t >= 1) sc += Ksh[tp[u] * 65 + tg[u]];
    }
  }
#pragma unroll
  for (int o = 16; o > 0; o >>= 1) sc += __shfl_xor_sync(0xffffffffu, sc, o);
  if (lane == 0) redx[wid] = sc;

  // ---- exp(K) column j, packed f32x2 pairs along i ----
  unsigned long long eK2[32];
#pragma unroll
  for (int p = 0; p < 32; p++) {
    float e0 = __expf(Ksh[(2 * p) * 65 + j]);
    float e1 = __expf(Ksh[(2 * p + 1) * 65 + j]);
    asm("mov.b64 %0, {%1, %2};" : "=l"(eK2[p]) : "f"(e0), "f"(e1));
  }

  // ---- init t = 0: f0 = exp(pot0 - C0), C0 = pot[0][0] (=> f_{0,0} = 1) ----
  float a0 = potb[j];
  if (j == 0) sbase = a0;
  float pc[U], pn[U];
#pragma unroll
  for (int u = 0; u < U; u++) {          // raw pot rows for t = 1..U (clamped)
    int t = 1 + u; if (t > L - 1) t = L - 1;
    pc[u] = potb[t * Nv + j];
  }
  __syncthreads();
  float sscore = redx[0] + redx[1];
  float C0 = sbase;
  float fj = __expf(a0 - C0);            // thread-local last f value
  fbuf[1][j] = fj;
  float acc = C0 * 1.4426950408889634f;  // running -log2(c_t); every thread keeps it
  __syncthreads();

  // ---- main scan. Chain per step: BAR -> LDS -> dot -> fj = s*pr -> STS -> BAR.
  //      Normalizer r = 1/f_{t-1,0} and acc += log2(f_{t-1,0}) are computed by
  //      EVERY thread from fbuf[rb][0] (already loaded for the dot) in the
  //      shadow of the FMA issue stream: no thread-0 tail on the barrier. ----
  for (int tb = 1; tb < L; tb += U) {
    const int nb = tb + U;
#pragma unroll
    for (int u = 0; u < U; u++) {        // prefetch next chunk (clamped, branch-free)
      int t = nb + u; if (t > L - 1) t = L - 1;
      pn[u] = potb[t * Nv + j];
    }
    float ec[U];                          // p_tj = exp(pot) for this chunk (off-chain)
#pragma unroll
    for (int u = 0; u < U; u++) ec[u] = __expf(pc[u]);
#pragma unroll
    for (int u = 0; u < U; u++) {
      const int tt = tb + u;
      if (tt >= L) break;                // uniform across block
      const int rb = tt & 1, wb = rb ^ 1;
      const ulonglong2* e2 = (const ulonglong2*)fbuf[rb];

      // shadow ops (depend only on first loaded element)
      float f0 = fbuf[rb][0];            // f_{t-1,0}
      float r;
      asm("rcp.approx.f32 %0, %1;" : "=f"(r) : "f"(f0));
      float pr = ec[u] * r;
      acc += __log2f(f0);

      unsigned long long a8[8] = {0ull,0ull,0ull,0ull,0ull,0ull,0ull,0ull};
#pragma unroll
      for (int q = 0; q < 16; q++) {     // 32 packed FMAs = 64 scalar MACs, 8 chains
        ulonglong2 v = e2[q];
        FMA_X2(a8[(2 * q) & 7], v.x, eK2[2 * q], a8[(2 * q) & 7]);
        FMA_X2(a8[(2 * q + 1) & 7], v.y, eK2[2 * q + 1], a8[(2 * q + 1) & 7]);
      }
      unsigned long long t0, t1, t2, t3, t01, t23, sA;
      ADD_X2(t0, a8[0], a8[1]);
      ADD_X2(t1, a8[2], a8[3]);
      ADD_X2(t2, a8[4], a8[5]);
      ADD_X2(t3, a8[6], a8[7]);
      ADD_X2(t01, t0, t1);
      ADD_X2(t23, t2, t3);
      ADD_X2(sA, t01, t23);
      float slo, shi;
      asm("mov.b64 {%0, %1}, %2;" : "=f"(slo), "=f"(shi) : "l"(sA));
      float s = slo + shi;

      fj = s * pr;                       // f_t,j = exp(alpha_t,j - alpha_{t-1,0})
      fbuf[wb][j] = fj;
      __syncthreads();
    }
#pragma unroll
    for (int u = 0; u < U; u++) pc[u] = pn[u];
  }

  // ---- finish: logZ = ln2 * (acc + log2(f_{L-1,0}) ... note acc covers tau<=L-2,
  //      so add the missing term via the reduce over f_{L-1}. ----
  float se = fj;
#pragma unroll
  for (int o = 16; o > 0; o >>= 1) se += __shfl_xor_sync(0xffffffffu, se, o);
  if (lane == 0) redm2[wid] = se;
  __syncthreads();

  if (j == 0) {
    float sumf = redm2[0] + redm2[1];
    float logZ = 0.6931471805599453f * (acc + __log2f(sumf));
    g_loss[b] = -(sscore - logZ) * w[b];
    __threadfence();
    unsigned old = atomicInc(&g_ctr, Bv - 1);  // wraps to 0 each full run
    slast = (old == (unsigned)(Bv - 1)) ? 1 : 0;
  }
  __syncthreads();
  if (slast) {
    float v = __ldcg(&g_loss[j]) + __ldcg(&g_loss[j + 64]);
#pragma unroll
    for (int o = 16; o > 0; o >>= 1) v += __shfl_xor_sync(0xffffffffu, v, o);
    if (lane == 0) redx[wid] = v;
    __syncthreads();
    if (j == 0) out[0] = (redx[0] + redx[1]) * (1.0f / (float)Bv);
  }
}

extern "C" void kernel_launch(void* const* d_in, const int* in_sizes, int n_in,
                              void* d_out, int out_size) {
  const float* pot    = (const float*)d_in[0];  // [128,1024,64] f32
  const int*   tags   = (const int*)  d_in[1];  // [128,1024] i32
  const int*   seqlen = (const int*)  d_in[2];  // [128] i32
  const float* K      = (const float*)d_in[3];  // [64,64] f32
  const float* w      = (const float*)d_in[4];  // [128] f32
  crf_kernel<<<Bv, Nv>>>(pot, tags, seqlen, K, w, (float*)d_out);
}